// round 7
// baseline (speedup 1.0000x reference)
#include <cuda_runtime.h>
#include <cuda_bf16.h>
#include <math.h>
#include <stdint.h>

#define BATCH 8
#define SEQ   2048
#define FDIM  512
#define DDIM  512
#define MTOT  (BATCH * SEQ)   // 16384

// ---------------- scratch (__device__ globals; no allocs allowed) ----------
__device__ __nv_bfloat16 g_xpe_h[(size_t)MTOT * FDIM];
__device__ __nv_bfloat16 g_xpe_l[(size_t)MTOT * FDIM];
__device__ __nv_bfloat16 g_Wt_h[3 * FDIM * DDIM];      // [z][n][k] (W transposed)
__device__ __nv_bfloat16 g_Wt_l[3 * FDIM * DDIM];
__device__ __nv_bfloat16 g_Q_h[(size_t)MTOT * DDIM];
__device__ __nv_bfloat16 g_Q_l[(size_t)MTOT * DDIM];
__device__ __nv_bfloat16 g_K_h[(size_t)MTOT * DDIM];
__device__ __nv_bfloat16 g_K_l[(size_t)MTOT * DDIM];
__device__ __nv_bfloat16 g_V_h[(size_t)MTOT * DDIM];
__device__ __nv_bfloat16 g_V_l[(size_t)MTOT * DDIM];
__device__ __nv_bfloat16 g_Vt_h[(size_t)MTOT * DDIM];  // [b][d][j]
__device__ __nv_bfloat16 g_Vt_l[(size_t)MTOT * DDIM];
__device__ float         g_scores[(size_t)BATCH * SEQ * SEQ];     // 134MB
__device__ __nv_bfloat16 g_attn_h[(size_t)BATCH * SEQ * SEQ];
__device__ __nv_bfloat16 g_attn_l[(size_t)BATCH * SEQ * SEQ];

// ---------------- PTX helpers ----------------------------------------------
__device__ __forceinline__ uint32_t s2u(const void* p) {
    return (uint32_t)__cvta_generic_to_shared(p);
}
__device__ __forceinline__ void cpa16(uint32_t dst, const void* src) {
    asm volatile("cp.async.cg.shared.global [%0], [%1], 16;\n" :: "r"(dst), "l"(src));
}
#define CP_COMMIT()  asm volatile("cp.async.commit_group;\n" ::: "memory")
#define CP_WAIT2()   asm volatile("cp.async.wait_group 2;\n" ::: "memory")

#define LDM4(r, addr) \
    asm volatile("ldmatrix.sync.aligned.m8n8.x4.shared.b16 {%0,%1,%2,%3}, [%4];" \
                 : "=r"((r)[0]), "=r"((r)[1]), "=r"((r)[2]), "=r"((r)[3]) : "r"(addr))

#define MMA16816(d, a, b0, b1) \
    asm volatile("mma.sync.aligned.m16n8k16.row.col.f32.bf16.bf16.f32 " \
                 "{%0,%1,%2,%3}, {%4,%5,%6,%7}, {%8,%9}, {%0,%1,%2,%3};" \
                 : "+f"((d)[0]), "+f"((d)[1]), "+f"((d)[2]), "+f"((d)[3]) \
                 : "r"((a)[0]), "r"((a)[1]), "r"((a)[2]), "r"((a)[3]), \
                   "r"(b0), "r"(b1))

// ---------------- GEMM: CTA 128x256, K-chunk 32, bf16x3, HMMA --------------
// Warp grid 2(M) x 4(N); warp tile 64x64 (mt=4, nt=8).
// smem per stage: Ah/Al 128 rows x 80B, Bh/Bl 256 rows x 80B (32 bf16 + pad)
#define A_PLANE    10240
#define B_PLANE    20480
#define OFF_AL     10240
#define OFF_BH     20480
#define OFF_BL     40960
#define STAGE_B    61440
#define SMEM_TOTAL (3 * STAGE_B)   // 184320

__device__ __forceinline__ void ld_stage(uint32_t sb,
    const __nv_bfloat16* Ah, const __nv_bfloat16* Al,
    const __nv_bfloat16* Bh, const __nv_bfloat16* Bl,
    int K, int k0, int tid)
{
#pragma unroll
    for (int i = 0; i < 2; i++) {          // A planes: 128 rows x 64B
        int ci = tid + i * 256;
        int r = ci >> 2, c = ci & 3;
        size_t ge = (size_t)r * K + k0 + c * 8;
        uint32_t so = r * 80 + c * 16;
        cpa16(sb + so,          Ah + ge);
        cpa16(sb + OFF_AL + so, Al + ge);
    }
#pragma unroll
    for (int i = 0; i < 4; i++) {          // B planes: 256 rows x 64B
        int ci = tid + i * 256;
        int r = ci >> 2, c = ci & 3;
        size_t ge = (size_t)r * K + k0 + c * 8;
        uint32_t so = r * 80 + c * 16;
        cpa16(sb + OFF_BH + so, Bh + ge);
        cpa16(sb + OFF_BL + so, Bl + ge);
    }
}

// EPI 0: fp32 C with alpha.  EPI 1: bf16 hi/lo split planes.
template <int EPI>
__device__ __forceinline__ void gemm_core(
    const __nv_bfloat16* __restrict__ Ah, const __nv_bfloat16* __restrict__ Al,
    const __nv_bfloat16* __restrict__ Bh, const __nv_bfloat16* __restrict__ Bl,
    int K, float alpha,
    float* __restrict__ C, int ldC,
    __nv_bfloat16* __restrict__ Ch, __nv_bfloat16* __restrict__ Cl)
{
    extern __shared__ __align__(128) char sm[];
    const uint32_t smb = s2u(sm);
    const int tid = threadIdx.x;
    const int w = tid >> 5, lane = tid & 31;
    const int wr = w & 1, wc = w >> 1;         // warp grid 2 (M) x 4 (N)
    const int q = lane & 7, sel = lane >> 3;   // ldmatrix addressing
    const int g = lane >> 2, t = lane & 3;     // fragment addressing

    // per-thread ldmatrix smem byte offsets (within plane); ks adds ks*32
    uint32_t aoff[4], boff[4];
#pragma unroll
    for (int mt = 0; mt < 4; mt++)
        aoff[mt] = (uint32_t)(wr * 64 + mt * 16 + (sel & 1) * 8 + q) * 80
                 + (uint32_t)(sel >> 1) * 16;
#pragma unroll
    for (int nb = 0; nb < 4; nb++)
        boff[nb] = (uint32_t)(wc * 64 + nb * 16 + (sel >> 1) * 8 + q) * 80
                 + (uint32_t)(sel & 1) * 16;

    const int n = K >> 5;   // K / 32 chunks

    ld_stage(smb,           Ah, Al, Bh, Bl, K, 0,  tid); CP_COMMIT();
    ld_stage(smb + STAGE_B, Ah, Al, Bh, Bl, K, 32, tid); CP_COMMIT();

    float acc[4][8][4];
#pragma unroll
    for (int mt = 0; mt < 4; mt++)
#pragma unroll
        for (int nt = 0; nt < 8; nt++)
#pragma unroll
            for (int r = 0; r < 4; r++) acc[mt][nt][r] = 0.0f;

    for (int i = 0; i < n; i++) {
        __syncthreads();   // compute(i-1) done everywhere -> safe to overwrite
        if (i + 2 < n)
            ld_stage(smb + ((i + 2) % 3) * STAGE_B, Ah, Al, Bh, Bl, K,
                     (i + 2) * 32, tid);
        CP_COMMIT();
        CP_WAIT2();
        __syncthreads();

        const uint32_t sb = smb + (i % 3) * STAGE_B;
#pragma unroll
        for (int ks = 0; ks < 2; ks++) {
            uint32_t ah[4][4], al[4][4], bh[4][4], bl[4][4];
#pragma unroll
            for (int mt = 0; mt < 4; mt++) {
                uint32_t ad = sb + aoff[mt] + ks * 32;
                LDM4(ah[mt], ad);
                LDM4(al[mt], ad + OFF_AL);
            }
#pragma unroll
            for (int nb = 0; nb < 4; nb++) {
                uint32_t bd = sb + OFF_BH + boff[nb] + ks * 32;
                LDM4(bh[nb], bd);
                LDM4(bl[nb], bd + B_PLANE);
            }
            // term-major issue order keeps dependent MMAs 32 apart
#pragma unroll
            for (int mt = 0; mt < 4; mt++)
#pragma unroll
                for (int nt = 0; nt < 8; nt++) {
                    const uint32_t* B0 = &bh[nt >> 1][(nt & 1) * 2];
                    MMA16816(acc[mt][nt], ah[mt], B0[0], B0[1]);
                }
#pragma unroll
            for (int mt = 0; mt < 4; mt++)
#pragma unroll
                for (int nt = 0; nt < 8; nt++) {
                    const uint32_t* B1 = &bl[nt >> 1][(nt & 1) * 2];
                    MMA16816(acc[mt][nt], ah[mt], B1[0], B1[1]);
                }
#pragma unroll
            for (int mt = 0; mt < 4; mt++)
#pragma unroll
                for (int nt = 0; nt < 8; nt++) {
                    const uint32_t* B0 = &bh[nt >> 1][(nt & 1) * 2];
                    MMA16816(acc[mt][nt], al[mt], B0[0], B0[1]);
                }
        }
    }

    // epilogue
#pragma unroll
    for (int mt = 0; mt < 4; mt++)
#pragma unroll
        for (int nt = 0; nt < 8; nt++) {
            int r0 = wr * 64 + mt * 16 + g;
            int c0 = wc * 64 + nt * 8 + 2 * t;
            if (EPI == 0) {
                float2 v0, v1;
                v0.x = alpha * acc[mt][nt][0]; v0.y = alpha * acc[mt][nt][1];
                v1.x = alpha * acc[mt][nt][2]; v1.y = alpha * acc[mt][nt][3];
                *(float2*)(C + (size_t)r0 * ldC + c0)       = v0;
                *(float2*)(C + (size_t)(r0 + 8) * ldC + c0) = v1;
            } else {
#pragma unroll
                for (int hh = 0; hh < 2; hh++) {
                    float v0 = acc[mt][nt][2 * hh + 0];
                    float v1 = acc[mt][nt][2 * hh + 1];
                    __nv_bfloat16 h0 = __float2bfloat16(v0);
                    __nv_bfloat16 h1 = __float2bfloat16(v1);
                    __nv_bfloat16 l0 = __float2bfloat16(v0 - __bfloat162float(h0));
                    __nv_bfloat16 l1 = __float2bfloat16(v1 - __bfloat162float(h1));
                    __nv_bfloat162 hp; hp.x = h0; hp.y = h1;
                    __nv_bfloat162 lp; lp.x = l0; lp.y = l1;
                    size_t off = (size_t)(r0 + 8 * hh) * ldC + c0;
                    *(__nv_bfloat162*)(Ch + off) = hp;
                    *(__nv_bfloat162*)(Cl + off) = lp;
                }
            }
        }
}

// ---------------- GEMM wrapper kernels -------------------------------------
__global__ void __launch_bounds__(256, 1) k_gemm_proj() {
    const int z = blockIdx.z;
    const size_t a0 = (size_t)blockIdx.y * 128 * FDIM;
    const size_t b0 = (size_t)z * FDIM * DDIM + (size_t)blockIdx.x * 256 * FDIM;
    __nv_bfloat16* Ch = (z == 0) ? g_Q_h : (z == 1) ? g_K_h : g_V_h;
    __nv_bfloat16* Cl = (z == 0) ? g_Q_l : (z == 1) ? g_K_l : g_V_l;
    const size_t c0 = (size_t)blockIdx.y * 128 * DDIM + blockIdx.x * 256;
    gemm_core<1>(g_xpe_h + a0, g_xpe_l + a0, g_Wt_h + b0, g_Wt_l + b0,
                 FDIM, 1.0f, nullptr, DDIM, Ch + c0, Cl + c0);
}

__global__ void __launch_bounds__(256, 1) k_gemm_scores() {
    const size_t b = blockIdx.z;
    const size_t a0 = b * SEQ * DDIM + (size_t)blockIdx.y * 128 * DDIM;
    const size_t b0 = b * SEQ * DDIM + (size_t)blockIdx.x * 256 * DDIM;
    const size_t c0 = b * SEQ * SEQ + (size_t)blockIdx.y * 128 * SEQ + blockIdx.x * 256;
    gemm_core<0>(g_Q_h + a0, g_Q_l + a0, g_K_h + b0, g_K_l + b0,
                 DDIM, 0.04419417382415922f, g_scores + c0, SEQ, nullptr, nullptr);
}

__global__ void __launch_bounds__(256, 1) k_gemm_av(float* __restrict__ out) {
    const size_t b = blockIdx.z;
    const size_t a0 = b * SEQ * SEQ + (size_t)blockIdx.y * 128 * SEQ;
    const size_t b0 = b * DDIM * SEQ + (size_t)blockIdx.x * 256 * SEQ;
    const size_t c0 = b * SEQ * DDIM + (size_t)blockIdx.y * 128 * DDIM + blockIdx.x * 256;
    gemm_core<0>(g_attn_h + a0, g_attn_l + a0, g_Vt_h + b0, g_Vt_l + b0,
                 SEQ, 1.0f, out + c0, DDIM, nullptr, nullptr);
}

// ---------------- aux kernels ----------------------------------------------
__global__ void __launch_bounds__(256) k_addpe_split(const float* __restrict__ x) {
    size_t idx = (size_t)blockIdx.x * 256 + threadIdx.x;
    int f = (int)(idx & (FDIM - 1));
    int s = (int)((idx >> 9) & (SEQ - 1));
    float e     = (float)(f & ~1) * (1.0f / (float)FDIM);
    float denom = powf(10000.0f, e);
    float angle = (float)s / denom;
    double r = fmod((double)angle, 6.283185307179586476925286766559);
    float a = (float)r;
    float pe = (f & 1) ? cosf(a) : sinf(a);
    float v = x[idx] + pe;
    __nv_bfloat16 h = __float2bfloat16(v);
    g_xpe_h[idx] = h;
    g_xpe_l[idx] = __float2bfloat16(v - __bfloat162float(h));
}

// transpose + split W: Wt[z][n][k] = W[z][k][n]
__global__ void __launch_bounds__(256) k_splitW(const float* __restrict__ Wq,
                                                const float* __restrict__ Wk,
                                                const float* __restrict__ Wv) {
    __shared__ float tsm[32][33];
    const int z = blockIdx.z;
    const float* W = (z == 0) ? Wq : (z == 1) ? Wk : Wv;
    const int k0 = blockIdx.y * 32, n0 = blockIdx.x * 32;
    const int tx = threadIdx.x & 31, ty = threadIdx.x >> 5;  // 32 x 8
#pragma unroll
    for (int i = 0; i < 32; i += 8)
        tsm[ty + i][tx] = W[(size_t)(k0 + ty + i) * DDIM + n0 + tx];
    __syncthreads();
#pragma unroll
    for (int i = 0; i < 32; i += 8) {
        float v = tsm[tx][ty + i];
        __nv_bfloat16 h = __float2bfloat16(v);
        size_t off = (size_t)z * FDIM * DDIM + (size_t)(n0 + ty + i) * FDIM + k0 + tx;
        g_Wt_h[off] = h;
        g_Wt_l[off] = __float2bfloat16(v - __bfloat162float(h));
    }
}

// transpose V planes: Vt[b][d][j] = V[b*2048+j][d]
__global__ void __launch_bounds__(256) k_transV() {
    __shared__ __nv_bfloat16 th[32][33];
    __shared__ __nv_bfloat16 tl[32][33];
    const int b = blockIdx.z;
    const int d0 = blockIdx.x * 32, j0 = blockIdx.y * 32;
    const int tx = threadIdx.x & 31, ty = threadIdx.x >> 5;
#pragma unroll
    for (int i = 0; i < 32; i += 8) {
        size_t off = (size_t)(b * SEQ + j0 + ty + i) * DDIM + d0 + tx;
        th[ty + i][tx] = g_V_h[off];
        tl[ty + i][tx] = g_V_l[off];
    }
    __syncthreads();
#pragma unroll
    for (int i = 0; i < 32; i += 8) {
        size_t off = (size_t)b * DDIM * SEQ + (size_t)(d0 + ty + i) * SEQ + j0 + tx;
        g_Vt_h[off] = th[tx][ty + i];
        g_Vt_l[off] = tl[tx][ty + i];
    }
}

// softmax over 2048 cols + split to bf16 planes
__global__ void __launch_bounds__(256) k_softmax_split() {
    const size_t rowoff = (size_t)blockIdx.x * SEQ;
    const float* p = g_scores + rowoff;
    const int tid = threadIdx.x;
    float v[8];
    float m = -1e30f;
#pragma unroll
    for (int i = 0; i < 8; i++) {
        v[i] = p[tid + i * 256];
        m = fmaxf(m, v[i]);
    }
    __shared__ float sh[8];
#pragma unroll
    for (int o = 16; o > 0; o >>= 1)
        m = fmaxf(m, __shfl_xor_sync(0xffffffffu, m, o));
    if ((tid & 31) == 0) sh[tid >> 5] = m;
    __syncthreads();
    m = sh[0];
#pragma unroll
    for (int w = 1; w < 8; w++) m = fmaxf(m, sh[w]);

    float s = 0.0f;
#pragma unroll
    for (int i = 0; i < 8; i++) {
        v[i] = expf(v[i] - m);
        s += v[i];
    }
#pragma unroll
    for (int o = 16; o > 0; o >>= 1)
        s += __shfl_xor_sync(0xffffffffu, s, o);
    __syncthreads();
    if ((tid & 31) == 0) sh[tid >> 5] = s;
    __syncthreads();
    s = 0.0f;
#pragma unroll
    for (int w = 0; w < 8; w++) s += sh[w];
    const float inv = 1.0f / s;
#pragma unroll
    for (int i = 0; i < 8; i++) {
        float a = v[i] * inv;
        __nv_bfloat16 h = __float2bfloat16(a);
        g_attn_h[rowoff + tid + i * 256] = h;
        g_attn_l[rowoff + tid + i * 256] = __float2bfloat16(a - __bfloat162float(h));
    }
}

// ---------------- launch ----------------------------------------------------
extern "C" void kernel_launch(void* const* d_in, const int* in_sizes, int n_in,
                              void* d_out, int out_size)
{
    const float* x  = (const float*)d_in[0];
    const float* Wq = (const float*)d_in[1];
    const float* Wk = (const float*)d_in[2];
    const float* Wv = (const float*)d_in[3];
    float* out = (float*)d_out;

    cudaFuncSetAttribute(k_gemm_proj,   cudaFuncAttributeMaxDynamicSharedMemorySize, SMEM_TOTAL);
    cudaFuncSetAttribute(k_gemm_scores, cudaFuncAttributeMaxDynamicSharedMemorySize, SMEM_TOTAL);
    cudaFuncSetAttribute(k_gemm_av,     cudaFuncAttributeMaxDynamicSharedMemorySize, SMEM_TOTAL);

    k_addpe_split<<<((size_t)MTOT * FDIM) / 256, 256>>>(x);
    k_splitW<<<dim3(DDIM / 32, FDIM / 32, 3), 256>>>(Wq, Wk, Wv);
    k_gemm_proj<<<dim3(DDIM / 256, MTOT / 128, 3), 256, SMEM_TOTAL>>>();
    k_transV<<<dim3(DDIM / 32, SEQ / 32, BATCH), 256>>>();
    k_gemm_scores<<<dim3(SEQ / 256, SEQ / 128, BATCH), 256, SMEM_TOTAL>>>();
    k_softmax_split<<<BATCH * SEQ, 256>>>();
    k_gemm_av<<<dim3(DDIM / 256, SEQ / 128, BATCH), 256, SMEM_TOTAL>>>(out);
}